// round 12
// baseline (speedup 1.0000x reference)
#include <cuda_runtime.h>
#include <math.h>

#define NB 16384
#define NM 50
#define ND 64
#define GRID 4096
#define FULLM 0xffffffffu

__global__ __launch_bounds__(32, 20)
void agree_kernel(
    const int* __restrict__ group_inputs,
    const int* __restrict__ item_inputs,
    const int* __restrict__ member_ids,
    const int* __restrict__ member_lengths,
    const float* __restrict__ user_table,
    const float* __restrict__ item_table,
    const float* __restrict__ group_table,
    const float* __restrict__ att_w1,
    const float* __restrict__ att_b1,
    const float* __restrict__ att_w2,
    const float* __restrict__ att_b2,
    const float* __restrict__ pred_w1,
    const float* __restrict__ pred_b1,
    const float* __restrict__ pred_w2,
    const float* __restrict__ pred_b2,
    float* __restrict__ out)
{
    // 4-member staging. One member = 72 words: d[0..31] at 0..31,
    // d[32..63] at 36..67 (pad kills bank aliasing between halves).
    __shared__ __align__(16) float s_me[4][72];
    __shared__ __align__(16) float s_new[3 * ND];   // [elem | g | item_e]

    const int lane = threadIdx.x & 31;
    const int c0 = lane & 15;   // att hidden unit / float4-chunk this lane owns
    const int h  = lane >> 4;   // d-half AND "own member" (within a pair)

    float* const s_item = &s_new[2 * ND];
    float* const meb = &s_me[0][0];                  // member stride 72 words
    const int stoff = 4 * c0 + ((c0 >= 8) ? 4 : 0);  // padded store offset

    // ======== CTA-lifetime constants (amortized over NB/GRID rows) ========
    float wc[32];                      // W1a column c0, d-half h
    #pragma unroll
    for (int k = 0; k < 32; k++) wc[k] = att_w1[(h * 32 + k) * 16 + c0];
    const float b1c = att_b1[c0];
    const float w2c = att_w2[c0];
    const float b2  = att_b2[0];

    const int j = lane & 7;            // predict hidden unit
    const int q = lane >> 3;           // predict k-quarter
    const float pb1 = pred_b1[j];
    const float pw2 = pred_w2[j];
    const float pb2 = pred_b2[0];

    #pragma unroll 1
    for (int b = blockIdx.x; b < NB; b += GRID) {
        // ---- row prologue: independent loads issued up front ----
        const int len = member_lengths[b];    // member m valid iff m <= len
        const int npairs = (len >> 1) + 1;
        const int nfull = npairs >> 1;        // double iterations (2 pairs)
        const int idsA = member_ids[b * NM + lane];
        const int idsB = (lane < NM - 32) ? member_ids[b * NM + 32 + lane] : 0;

        const float4 it4 =
            ((const float4*)(item_table + (size_t)item_inputs[b] * ND))[c0];
        // prefetch group row now — its latency hides under the whole loop
        const float4 grp =
            ((const float4*)(group_table + (size_t)group_inputs[b] * ND))[c0];

        ((float4*)s_item)[c0] = it4;   // both halves write identical data
        __syncwarp();

        // preload: pair0 member h, and (if present) pair1 member h
        float4 rA, rB;
        {
            int mid = __shfl_sync(FULLM, idsA, h);
            rA = ((const float4*)(user_table + (size_t)mid * ND))[c0];
        }
        if (npairs >= 2) {
            int mid = __shfl_sync(FULLM, idsA, 2 + h);
            rB = ((const float4*)(user_table + (size_t)mid * ND))[c0];
        }

        // cconst[c0] = att_b1 + item_e @ W1b, split per d-half + combine
        float cconst;
        {
            float cc = 0.f;
            const float4* si4 = (const float4*)(s_item + h * 32);
            #pragma unroll
            for (int dd = 0; dd < 8; dd++) {
                float4 v = si4[dd];
                int db = (ND + h * 32 + 4 * dd) * 16 + c0;
                cc = fmaf(v.x, att_w1[db],      cc);
                cc = fmaf(v.y, att_w1[db + 16], cc);
                cc = fmaf(v.z, att_w1[db + 32], cc);
                cc = fmaf(v.w, att_w1[db + 48], cc);
            }
            cconst = cc + __shfl_xor_sync(FULLM, cc, 16) + b1c;
        }

        // plain-exp softmax (scores O(0.3) by construction — no max shift)
        float dsum = 0.f;
        float4 gq = make_float4(0.f, 0.f, 0.f, 0.f);

        #pragma unroll 1
        for (int u = 0; u < nfull; u++) {
            const float4 curA = rA;   // own member of pair 2u   (m = 4u+h)
            const float4 curB = rB;   // own member of pair 2u+1 (m = 4u+2+h)

            // stage 4 members
            *(float4*)(meb + h * 72 + stoff)       = curA;
            *(float4*)(meb + 144 + h * 72 + stoff) = curB;
            __syncwarp();

            // prefetch pairs 2u+2 / 2u+3 (warp-uniform guards)
            if (2 * u + 2 < npairs) {
                int m = 4 * u + 4 + h;
                int mid = __shfl_sync(FULLM, (m < 32) ? idsA : idsB, m & 31);
                rA = ((const float4*)(user_table + (size_t)mid * ND))[c0];
            }
            if (2 * u + 3 < npairs) {
                int m = 4 * u + 6 + h;
                int mid = __shfl_sync(FULLM, (m < 32) ? idsA : idsB, m & 31);
                rB = ((const float4*)(user_table + (size_t)mid * ND))[c0];
            }

            // dots: 4 members over this lane's 32-d slice; 8 interleaved accs
            const float4* a0 = (const float4*)(meb + h * 36);
            const float4* a1 = (const float4*)(meb + 72 + h * 36);
            const float4* bb0 = (const float4*)(meb + 144 + h * 36);
            const float4* bb1 = (const float4*)(meb + 216 + h * 36);
            float sA0[2] = {0.f, 0.f}, sA1[2] = {0.f, 0.f};
            float sB0[2] = {0.f, 0.f}, sB1[2] = {0.f, 0.f};
            #pragma unroll
            for (int i = 0; i < 8; i++) {
                const int par = i & 1;
                float4 x = a0[i];
                sA0[par] = fmaf(x.x, wc[4*i+0], sA0[par]);
                sA0[par] = fmaf(x.y, wc[4*i+1], sA0[par]);
                sA0[par] = fmaf(x.z, wc[4*i+2], sA0[par]);
                sA0[par] = fmaf(x.w, wc[4*i+3], sA0[par]);
                float4 y = a1[i];
                sA1[par] = fmaf(y.x, wc[4*i+0], sA1[par]);
                sA1[par] = fmaf(y.y, wc[4*i+1], sA1[par]);
                sA1[par] = fmaf(y.z, wc[4*i+2], sA1[par]);
                sA1[par] = fmaf(y.w, wc[4*i+3], sA1[par]);
                float4 z = bb0[i];
                sB0[par] = fmaf(z.x, wc[4*i+0], sB0[par]);
                sB0[par] = fmaf(z.y, wc[4*i+1], sB0[par]);
                sB0[par] = fmaf(z.z, wc[4*i+2], sB0[par]);
                sB0[par] = fmaf(z.w, wc[4*i+3], sB0[par]);
                float4 w = bb1[i];
                sB1[par] = fmaf(w.x, wc[4*i+0], sB1[par]);
                sB1[par] = fmaf(w.y, wc[4*i+1], sB1[par]);
                sB1[par] = fmaf(w.z, wc[4*i+2], sB1[par]);
                sB1[par] = fmaf(w.w, wc[4*i+3], sB1[par]);
            }
            float p0 = sA0[0] + sA0[1];   // pair A member0, this d-half
            float p1 = sA1[0] + sA1[1];   // pair A member1
            float q0 = sB0[0] + sB0[1];   // pair B member0
            float q1 = sB1[0] + sB1[1];   // pair B member1

            // own-member assembly for both pairs (independent shfl chains)
            float uA = h ? p1 : p0, vA = h ? p0 : p1;
            float uB = h ? q1 : q0, vB = h ? q0 : q1;
            float AA = uA + __shfl_xor_sync(FULLM, vA, 16);
            float AB = uB + __shfl_xor_sync(FULLM, vB, 16);
            float tA = fmaxf(AA + cconst, 0.f) * w2c;
            float tB = fmaxf(AB + cconst, 0.f) * w2c;

            // interleaved butterflies over the 16 columns of each half
            tA += __shfl_xor_sync(FULLM, tA, 1);
            tB += __shfl_xor_sync(FULLM, tB, 1);
            tA += __shfl_xor_sync(FULLM, tA, 2);
            tB += __shfl_xor_sync(FULLM, tB, 2);
            tA += __shfl_xor_sync(FULLM, tA, 4);
            tB += __shfl_xor_sync(FULLM, tB, 4);
            tA += __shfl_xor_sync(FULLM, tA, 8);
            tB += __shfl_xor_sync(FULLM, tB, 8);

            // own-member weights (two independent exps)
            float eA = (4 * u + h     <= len) ? __expf(tA + b2) : 0.f;
            float eB = (4 * u + 2 + h <= len) ? __expf(tB + b2) : 0.f;
            dsum += eA + eB;
            gq.x = fmaf(eA, curA.x, fmaf(eB, curB.x, gq.x));
            gq.y = fmaf(eA, curA.y, fmaf(eB, curB.y, gq.y));
            gq.z = fmaf(eA, curA.z, fmaf(eB, curB.z, gq.z));
            gq.w = fmaf(eA, curA.w, fmaf(eB, curB.w, gq.w));
        }

        // ---- remainder pair (npairs odd): members 4*nfull + {0,1} in rA ----
        if (npairs & 1) {
            const float4 cur = rA;
            *(float4*)(meb + h * 72 + stoff) = cur;
            __syncwarp();

            const float4* me0 = (const float4*)(meb + h * 36);
            const float4* me1 = (const float4*)(meb + 72 + h * 36);
            float s0[2] = {0.f, 0.f}, s1[2] = {0.f, 0.f};
            #pragma unroll
            for (int i = 0; i < 8; i++) {
                const int par = i & 1;
                float4 x = me0[i];
                s0[par] = fmaf(x.x, wc[4*i+0], s0[par]);
                s0[par] = fmaf(x.y, wc[4*i+1], s0[par]);
                s0[par] = fmaf(x.z, wc[4*i+2], s0[par]);
                s0[par] = fmaf(x.w, wc[4*i+3], s0[par]);
                float4 y = me1[i];
                s1[par] = fmaf(y.x, wc[4*i+0], s1[par]);
                s1[par] = fmaf(y.y, wc[4*i+1], s1[par]);
                s1[par] = fmaf(y.z, wc[4*i+2], s1[par]);
                s1[par] = fmaf(y.w, wc[4*i+3], s1[par]);
            }
            float p0 = s0[0] + s0[1];
            float p1 = s1[0] + s1[1];

            float u2 = h ? p1 : p0, v2 = h ? p0 : p1;
            float A = u2 + __shfl_xor_sync(FULLM, v2, 16);
            float t = fmaxf(A + cconst, 0.f) * w2c;
            t += __shfl_xor_sync(FULLM, t, 1);
            t += __shfl_xor_sync(FULLM, t, 2);
            t += __shfl_xor_sync(FULLM, t, 4);
            t += __shfl_xor_sync(FULLM, t, 8);

            float e = (4 * nfull + h <= len) ? __expf(t + b2) : 0.f;
            dsum += e;
            gq.x = fmaf(e, cur.x, gq.x);
            gq.y = fmaf(e, cur.y, gq.y);
            gq.z = fmaf(e, cur.z, gq.z);
            gq.w = fmaf(e, cur.w, gq.w);
        }

        // ---- cross-half combine: pooled g + group embedding (prefetched) ----
        gq.x += __shfl_xor_sync(FULLM, gq.x, 16);
        gq.y += __shfl_xor_sync(FULLM, gq.y, 16);
        gq.z += __shfl_xor_sync(FULLM, gq.z, 16);
        gq.w += __shfl_xor_sync(FULLM, gq.w, 16);
        dsum += __shfl_xor_sync(FULLM, dsum, 16);
        const float inv = 1.0f / dsum;

        float4 gg, el;
        gg.x = fmaf(gq.x, inv, grp.x);  el.x = gg.x * it4.x;
        gg.y = fmaf(gq.y, inv, grp.y);  el.y = gg.y * it4.y;
        gg.z = fmaf(gq.z, inv, grp.z);  el.z = gg.z * it4.z;
        gg.w = fmaf(gq.w, inv, grp.w);  el.w = gg.w * it4.w;

        // both halves hold identical values; duplicate stores are benign
        ((float4*)&s_new[0])[c0]  = el;   // elem
        ((float4*)&s_new[ND])[c0] = gg;   // g (item already at s_new[2*ND])
        __syncwarp();

        // ---- predict MLP: new_e[192] -> 8 -> 1 -> sigmoid (float4 LDS) ----
        float ph = 0.f;
        {
            const float4* sn4 = (const float4*)s_new;
            #pragma unroll
            for (int i = 0; i < 12; i++) {
                float4 a = sn4[q * 12 + i];
                int k = q * 48 + 4 * i;
                ph = fmaf(a.x, pred_w1[k * 8 + j],       ph);
                ph = fmaf(a.y, pred_w1[(k + 1) * 8 + j], ph);
                ph = fmaf(a.z, pred_w1[(k + 2) * 8 + j], ph);
                ph = fmaf(a.w, pred_w1[(k + 3) * 8 + j], ph);
            }
        }
        ph += __shfl_xor_sync(FULLM, ph, 8);
        ph += __shfl_xor_sync(FULLM, ph, 16);

        float t2 = fmaxf(ph + pb1, 0.f) * pw2;
        t2 += __shfl_xor_sync(FULLM, t2, 1);
        t2 += __shfl_xor_sync(FULLM, t2, 2);
        t2 += __shfl_xor_sync(FULLM, t2, 4);

        if (lane == 0) {
            float z = t2 + pb2;
            out[b] = 1.0f / (1.0f + __expf(-z));
        }
        __syncwarp();   // protect s_new/s_me reuse across rows
    }
}

extern "C" void kernel_launch(void* const* d_in, const int* in_sizes, int n_in,
                              void* d_out, int out_size) {
    (void)in_sizes; (void)n_in; (void)out_size;
    agree_kernel<<<GRID, 32>>>(
        (const int*)d_in[0],   // group_inputs
        (const int*)d_in[1],   // item_inputs
        (const int*)d_in[2],   // member_ids
        (const int*)d_in[3],   // member_lengths
        (const float*)d_in[4], // user_table
        (const float*)d_in[5], // item_table
        (const float*)d_in[6], // group_table
        (const float*)d_in[7], // att_w1
        (const float*)d_in[8], // att_b1
        (const float*)d_in[9], // att_w2
        (const float*)d_in[10],// att_b2
        (const float*)d_in[11],// pred_w1
        (const float*)d_in[12],// pred_b1
        (const float*)d_in[13],// pred_w2
        (const float*)d_in[14],// pred_b2
        (float*)d_out);
}

// round 13
// speedup vs baseline: 1.1753x; 1.1753x over previous
#include <cuda_runtime.h>
#include <math.h>

#define NB 16384
#define NM 50
#define ND 64
#define FULLM 0xffffffffu

__global__ __launch_bounds__(32, 20)
void agree_kernel(
    const int* __restrict__ group_inputs,
    const int* __restrict__ item_inputs,
    const int* __restrict__ member_ids,
    const int* __restrict__ member_lengths,
    const float* __restrict__ user_table,
    const float* __restrict__ item_table,
    const float* __restrict__ group_table,
    const float* __restrict__ att_w1,
    const float* __restrict__ att_b1,
    const float* __restrict__ att_w2,
    const float* __restrict__ att_b2,
    const float* __restrict__ pred_w1,
    const float* __restrict__ pred_b1,
    const float* __restrict__ pred_w2,
    const float* __restrict__ pred_b2,
    float* __restrict__ out)
{
    // 4-member staging. One member = 72 words: d[0..31] at 0..31,
    // d[32..63] at 36..67 (pad kills bank aliasing between halves).
    __shared__ __align__(16) float s_me[4][72];
    __shared__ __align__(16) float s_new[3 * ND];   // [elem | g | item_e]

    const int lane = threadIdx.x & 31;
    const int b = blockIdx.x;

    const int c0 = lane & 15;   // att hidden unit / float4-chunk this lane owns
    const int h  = lane >> 4;   // d-half AND "own member" (within a pair)

    float* s_item = &s_new[2 * ND];

    // ---- row prologue: independent loads issued up front ----
    const int len = member_lengths[b];       // member m valid iff m <= len
    const int npairs = (len >> 1) + 1;
    const int nfull = (npairs + 1) >> 1;     // double iterations (2 pairs each)

    const float4 it4 =
        ((const float4*)(item_table + (size_t)item_inputs[b] * ND))[c0];
    // prefetch group row now — its latency hides under the whole loop
    const float4 grp =
        ((const float4*)(group_table + (size_t)group_inputs[b] * ND))[c0];

    ((float4*)s_item)[c0] = it4;   // both halves write identical data
    __syncwarp();

    // ---- all member ids into registers ----
    const int idsA = member_ids[b * NM + lane];
    const int idsB = (lane < NM - 32) ? member_ids[b * NM + 32 + lane] : 0;

    // ---- W1a slice: column c0, d-range [h*32, h*32+32)  (32 regs) ----
    float wc[32];
    #pragma unroll
    for (int k = 0; k < 32; k++) wc[k] = att_w1[(h * 32 + k) * 16 + c0];

    // ---- cconst[c0] = att_b1 + item_e @ W1b, split per d-half + combine ----
    float cconst;
    {
        float cc = 0.f;
        const float4* si4 = (const float4*)(s_item + h * 32);
        #pragma unroll
        for (int dd = 0; dd < 8; dd++) {
            float4 v = si4[dd];
            int db = (ND + h * 32 + 4 * dd) * 16 + c0;
            cc = fmaf(v.x, att_w1[db],      cc);
            cc = fmaf(v.y, att_w1[db + 16], cc);
            cc = fmaf(v.z, att_w1[db + 32], cc);
            cc = fmaf(v.w, att_w1[db + 48], cc);
        }
        cconst = cc + __shfl_xor_sync(FULLM, cc, 16) + att_b1[c0];
    }

    const float w2c = att_w2[c0];
    const float b2  = att_b2[0];

    // plain-exp softmax (scores O(0.3) by construction — no max shift)
    float dsum = 0.f;
    float4 gq = make_float4(0.f, 0.f, 0.f, 0.f);

    // ---- preload: pair0 member h; pair1 member h or zeros (phantom pair) ----
    float4 rA, rB = make_float4(0.f, 0.f, 0.f, 0.f);
    {
        int mid = __shfl_sync(FULLM, idsA, h);
        rA = ((const float4*)(user_table + (size_t)mid * ND))[c0];
    }
    if (npairs >= 2) {
        int mid = __shfl_sync(FULLM, idsA, 2 + h);
        rB = ((const float4*)(user_table + (size_t)mid * ND))[c0];
    }

    float* const meb = &s_me[0][0];                  // member stride 72 words
    const int stoff = 4 * c0 + ((c0 >= 8) ? 4 : 0);  // padded store offset

    #pragma unroll 1
    for (int u = 0; u < nfull; u++) {
        const float4 curA = rA;   // own member of pair 2u   (m = 4u+h)
        const float4 curB = rB;   // own member of pair 2u+1 (m = 4u+2+h)

        // stage 4 members (phantom pair stages zeros/stale — masked by eB=0)
        *(float4*)(meb + h * 72 + stoff)       = curA;
        *(float4*)(meb + 144 + h * 72 + stoff) = curB;
        __syncwarp();

        // prefetch pairs 2u+2 / 2u+3 (warp-uniform guards)
        if (2 * u + 2 < npairs) {
            int m = 4 * u + 4 + h;
            int mid = __shfl_sync(FULLM, (m < 32) ? idsA : idsB, m & 31);
            rA = ((const float4*)(user_table + (size_t)mid * ND))[c0];
        }
        if (2 * u + 3 < npairs) {
            int m = 4 * u + 6 + h;
            int mid = __shfl_sync(FULLM, (m < 32) ? idsA : idsB, m & 31);
            rB = ((const float4*)(user_table + (size_t)mid * ND))[c0];
        }

        // dots: 4 members over this lane's 32-d slice; 8 interleaved accs
        const float4* a0 = (const float4*)(meb + h * 36);
        const float4* a1 = (const float4*)(meb + 72 + h * 36);
        const float4* bb0 = (const float4*)(meb + 144 + h * 36);
        const float4* bb1 = (const float4*)(meb + 216 + h * 36);
        float sA0[2] = {0.f, 0.f}, sA1[2] = {0.f, 0.f};
        float sB0[2] = {0.f, 0.f}, sB1[2] = {0.f, 0.f};
        #pragma unroll
        for (int i = 0; i < 8; i++) {
            const int par = i & 1;
            float4 x = a0[i];
            sA0[par] = fmaf(x.x, wc[4*i+0], sA0[par]);
            sA0[par] = fmaf(x.y, wc[4*i+1], sA0[par]);
            sA0[par] = fmaf(x.z, wc[4*i+2], sA0[par]);
            sA0[par] = fmaf(x.w, wc[4*i+3], sA0[par]);
            float4 y = a1[i];
            sA1[par] = fmaf(y.x, wc[4*i+0], sA1[par]);
            sA1[par] = fmaf(y.y, wc[4*i+1], sA1[par]);
            sA1[par] = fmaf(y.z, wc[4*i+2], sA1[par]);
            sA1[par] = fmaf(y.w, wc[4*i+3], sA1[par]);
            float4 z = bb0[i];
            sB0[par] = fmaf(z.x, wc[4*i+0], sB0[par]);
            sB0[par] = fmaf(z.y, wc[4*i+1], sB0[par]);
            sB0[par] = fmaf(z.z, wc[4*i+2], sB0[par]);
            sB0[par] = fmaf(z.w, wc[4*i+3], sB0[par]);
            float4 w = bb1[i];
            sB1[par] = fmaf(w.x, wc[4*i+0], sB1[par]);
            sB1[par] = fmaf(w.y, wc[4*i+1], sB1[par]);
            sB1[par] = fmaf(w.z, wc[4*i+2], sB1[par]);
            sB1[par] = fmaf(w.w, wc[4*i+3], sB1[par]);
        }
        float p0 = sA0[0] + sA0[1];   // pair A member0, this d-half
        float p1 = sA1[0] + sA1[1];   // pair A member1
        float q0 = sB0[0] + sB0[1];   // pair B member0
        float q1 = sB1[0] + sB1[1];   // pair B member1

        // own-member assembly for both pairs (independent shfl chains)
        float uA = h ? p1 : p0, vA = h ? p0 : p1;
        float uB = h ? q1 : q0, vB = h ? q0 : q1;
        float AA = uA + __shfl_xor_sync(FULLM, vA, 16);
        float AB = uB + __shfl_xor_sync(FULLM, vB, 16);
        float tA = fmaxf(AA + cconst, 0.f) * w2c;
        float tB = fmaxf(AB + cconst, 0.f) * w2c;

        // interleaved butterflies over the 16 columns of each half
        tA += __shfl_xor_sync(FULLM, tA, 1);
        tB += __shfl_xor_sync(FULLM, tB, 1);
        tA += __shfl_xor_sync(FULLM, tA, 2);
        tB += __shfl_xor_sync(FULLM, tB, 2);
        tA += __shfl_xor_sync(FULLM, tA, 4);
        tB += __shfl_xor_sync(FULLM, tB, 4);
        tA += __shfl_xor_sync(FULLM, tA, 8);
        tB += __shfl_xor_sync(FULLM, tB, 8);

        // own-member weights (two independent exps); phantom pair -> eB = 0
        float eA = (4 * u + h     <= len) ? __expf(tA + b2) : 0.f;
        float eB = (4 * u + 2 + h <= len) ? __expf(tB + b2) : 0.f;
        dsum += eA + eB;
        gq.x = fmaf(eA, curA.x, fmaf(eB, curB.x, gq.x));
        gq.y = fmaf(eA, curA.y, fmaf(eB, curB.y, gq.y));
        gq.z = fmaf(eA, curA.z, fmaf(eB, curB.z, gq.z));
        gq.w = fmaf(eA, curA.w, fmaf(eB, curB.w, gq.w));
    }

    // ---- cross-half combine: pooled g + group embedding (prefetched) ----
    gq.x += __shfl_xor_sync(FULLM, gq.x, 16);
    gq.y += __shfl_xor_sync(FULLM, gq.y, 16);
    gq.z += __shfl_xor_sync(FULLM, gq.z, 16);
    gq.w += __shfl_xor_sync(FULLM, gq.w, 16);
    dsum += __shfl_xor_sync(FULLM, dsum, 16);
    const float inv = 1.0f / dsum;

    float4 gg, el;
    gg.x = fmaf(gq.x, inv, grp.x);  el.x = gg.x * it4.x;
    gg.y = fmaf(gq.y, inv, grp.y);  el.y = gg.y * it4.y;
    gg.z = fmaf(gq.z, inv, grp.z);  el.z = gg.z * it4.z;
    gg.w = fmaf(gq.w, inv, grp.w);  el.w = gg.w * it4.w;

    // both halves hold identical values; duplicate stores are benign
    ((float4*)&s_new[0])[c0]  = el;   // elem
    ((float4*)&s_new[ND])[c0] = gg;   // g   (item already at s_new[2*ND])
    __syncwarp();

    // ---- predict MLP: new_e[192] -> 8 -> 1 -> sigmoid (float4 LDS) ----
    const int j = lane & 7;        // hidden unit
    const int q = lane >> 3;       // k-quarter (48 elems each)
    float ph = 0.f;
    {
        const float4* sn4 = (const float4*)s_new;
        #pragma unroll
        for (int i = 0; i < 12; i++) {
            float4 a = sn4[q * 12 + i];
            int k = q * 48 + 4 * i;
            ph = fmaf(a.x, pred_w1[k * 8 + j],       ph);
            ph = fmaf(a.y, pred_w1[(k + 1) * 8 + j], ph);
            ph = fmaf(a.z, pred_w1[(k + 2) * 8 + j], ph);
            ph = fmaf(a.w, pred_w1[(k + 3) * 8 + j], ph);
        }
    }
    ph += __shfl_xor_sync(FULLM, ph, 8);
    ph += __shfl_xor_sync(FULLM, ph, 16);

    float hj = fmaxf(ph + pred_b1[j], 0.f);
    float t2 = hj * pred_w2[j];
    t2 += __shfl_xor_sync(FULLM, t2, 1);
    t2 += __shfl_xor_sync(FULLM, t2, 2);
    t2 += __shfl_xor_sync(FULLM, t2, 4);

    if (lane == 0) {
        float z = t2 + pred_b2[0];
        out[b] = 1.0f / (1.0f + __expf(-z));
    }
}

extern "C" void kernel_launch(void* const* d_in, const int* in_sizes, int n_in,
                              void* d_out, int out_size) {
    (void)in_sizes; (void)n_in; (void)out_size;
    agree_kernel<<<NB, 32>>>(
        (const int*)d_in[0],   // group_inputs
        (const int*)d_in[1],   // item_inputs
        (const int*)d_in[2],   // member_ids
        (const int*)d_in[3],   // member_lengths
        (const float*)d_in[4], // user_table
        (const float*)d_in[5], // item_table
        (const float*)d_in[6], // group_table
        (const float*)d_in[7], // att_w1
        (const float*)d_in[8], // att_b1
        (const float*)d_in[9], // att_w2
        (const float*)d_in[10],// att_b2
        (const float*)d_in[11],// pred_w1
        (const float*)d_in[12],// pred_b1
        (const float*)d_in[13],// pred_w2
        (const float*)d_in[14],// pred_b2
        (float*)d_out);
}

// round 14
// speedup vs baseline: 1.1798x; 1.0039x over previous
#include <cuda_runtime.h>
#include <math.h>

#define NB 16384
#define NM 50
#define ND 64
#define FULLM 0xffffffffu

__global__ __launch_bounds__(32, 20)
void agree_kernel(
    const int* __restrict__ group_inputs,
    const int* __restrict__ item_inputs,
    const int* __restrict__ member_ids,
    const int* __restrict__ member_lengths,
    const float* __restrict__ user_table,
    const float* __restrict__ item_table,
    const float* __restrict__ group_table,
    const float* __restrict__ att_w1,
    const float* __restrict__ att_b1,
    const float* __restrict__ att_w2,
    const float* __restrict__ att_b2,
    const float* __restrict__ pred_w1,
    const float* __restrict__ pred_b1,
    const float* __restrict__ pred_w2,
    const float* __restrict__ pred_b2,
    float* __restrict__ out)
{
    // 4-member staging. One member = 72 words: d[0..31] at 0..31,
    // d[32..63] at 36..67 (pad kills bank aliasing between halves).
    __shared__ __align__(16) float s_me[4][72];
    __shared__ __align__(16) float s_new[3 * ND];   // [elem | g | item_e]

    const int lane = threadIdx.x & 31;
    const int b = blockIdx.x;

    const int c0 = lane & 15;   // att hidden unit / float4-chunk this lane owns
    const int h  = lane >> 4;   // d-half AND "own member" (within a pair)

    float* s_item = &s_new[2 * ND];

    // ---- item embedding + group-row prefetch (independent LDGs up front) ----
    const float4 it4 =
        ((const float4*)(item_table + (size_t)item_inputs[b] * ND))[c0];
    const float4 grp =
        ((const float4*)(group_table + (size_t)group_inputs[b] * ND))[c0];
    ((float4*)s_item)[c0] = it4;
    __syncwarp();

    // ---- all member ids into registers ----
    const int idsA = member_ids[b * NM + lane];
    const int idsB = (lane < NM - 32) ? member_ids[b * NM + 32 + lane] : 0;

    // ---- W1a slice: column c0, d-range [h*32, h*32+32)  (32 regs) ----
    float wc[32];
    #pragma unroll
    for (int k = 0; k < 32; k++) wc[k] = att_w1[(h * 32 + k) * 16 + c0];

    // ---- cconst[c0] = att_b1 + item_e @ W1b, split per d-half + combine ----
    float cconst;
    {
        float cc = 0.f;
        const float4* si4 = (const float4*)(s_item + h * 32);
        #pragma unroll
        for (int dd = 0; dd < 8; dd++) {
            float4 v = si4[dd];
            int db = (ND + h * 32 + 4 * dd) * 16 + c0;
            cc = fmaf(v.x, att_w1[db],      cc);
            cc = fmaf(v.y, att_w1[db + 16], cc);
            cc = fmaf(v.z, att_w1[db + 32], cc);
            cc = fmaf(v.w, att_w1[db + 48], cc);
        }
        cconst = cc + __shfl_xor_sync(FULLM, cc, 16) + att_b1[c0];
    }

    const float w2c = att_w2[c0];
    const float b2  = att_b2[0];
    const int  len  = member_lengths[b];     // member m valid iff m <= len
    const int  npairs = (len >> 1) + 1;
    const int  nfull = npairs >> 1;          // double iterations (2 pairs each)

    // plain-exp softmax (scores O(0.3) by construction — no max shift)
    float dsum = 0.f;
    float4 gq = make_float4(0.f, 0.f, 0.f, 0.f);

    // ---- preload: pair0 member h, and (if present) pair1 member h ----
    float4 rA, rB;
    {
        int mid = __shfl_sync(FULLM, idsA, h);
        rA = ((const float4*)(user_table + (size_t)mid * ND))[c0];
    }
    if (npairs >= 2) {
        int mid = __shfl_sync(FULLM, idsA, 2 + h);
        rB = ((const float4*)(user_table + (size_t)mid * ND))[c0];
    }

    float* const meb = &s_me[0][0];                  // member stride 72 words
    const int stoff = 4 * c0 + ((c0 >= 8) ? 4 : 0);  // padded store offset

    #pragma unroll 1
    for (int u = 0; u < nfull; u++) {
        const float4 curA = rA;   // own member of pair 2u   (m = 4u+h)
        const float4 curB = rB;   // own member of pair 2u+1 (m = 4u+2+h)

        // stage 4 members
        *(float4*)(meb + h * 72 + stoff)       = curA;
        *(float4*)(meb + 144 + h * 72 + stoff) = curB;
        __syncwarp();

        // prefetch pairs 2u+2 / 2u+3 (warp-uniform guards)
        if (2 * u + 2 < npairs) {
            int m = 4 * u + 4 + h;
            int mid = __shfl_sync(FULLM, (m < 32) ? idsA : idsB, m & 31);
            rA = ((const float4*)(user_table + (size_t)mid * ND))[c0];
        }
        if (2 * u + 3 < npairs) {
            int m = 4 * u + 6 + h;
            int mid = __shfl_sync(FULLM, (m < 32) ? idsA : idsB, m & 31);
            rB = ((const float4*)(user_table + (size_t)mid * ND))[c0];
        }

        // dots: 4 members over this lane's 32-d slice; 8 interleaved accs
        const float4* a0 = (const float4*)(meb + h * 36);
        const float4* a1 = (const float4*)(meb + 72 + h * 36);
        const float4* bb0 = (const float4*)(meb + 144 + h * 36);
        const float4* bb1 = (const float4*)(meb + 216 + h * 36);
        float sA0[2] = {0.f, 0.f}, sA1[2] = {0.f, 0.f};
        float sB0[2] = {0.f, 0.f}, sB1[2] = {0.f, 0.f};
        #pragma unroll
        for (int i = 0; i < 8; i++) {
            const int par = i & 1;
            float4 x = a0[i];
            sA0[par] = fmaf(x.x, wc[4*i+0], sA0[par]);
            sA0[par] = fmaf(x.y, wc[4*i+1], sA0[par]);
            sA0[par] = fmaf(x.z, wc[4*i+2], sA0[par]);
            sA0[par] = fmaf(x.w, wc[4*i+3], sA0[par]);
            float4 y = a1[i];
            sA1[par] = fmaf(y.x, wc[4*i+0], sA1[par]);
            sA1[par] = fmaf(y.y, wc[4*i+1], sA1[par]);
            sA1[par] = fmaf(y.z, wc[4*i+2], sA1[par]);
            sA1[par] = fmaf(y.w, wc[4*i+3], sA1[par]);
            float4 z = bb0[i];
            sB0[par] = fmaf(z.x, wc[4*i+0], sB0[par]);
            sB0[par] = fmaf(z.y, wc[4*i+1], sB0[par]);
            sB0[par] = fmaf(z.z, wc[4*i+2], sB0[par]);
            sB0[par] = fmaf(z.w, wc[4*i+3], sB0[par]);
            float4 w = bb1[i];
            sB1[par] = fmaf(w.x, wc[4*i+0], sB1[par]);
            sB1[par] = fmaf(w.y, wc[4*i+1], sB1[par]);
            sB1[par] = fmaf(w.z, wc[4*i+2], sB1[par]);
            sB1[par] = fmaf(w.w, wc[4*i+3], sB1[par]);
        }
        float p0 = sA0[0] + sA0[1];   // pair A member0, this d-half
        float p1 = sA1[0] + sA1[1];   // pair A member1
        float q0 = sB0[0] + sB0[1];   // pair B member0
        float q1 = sB1[0] + sB1[1];   // pair B member1

        // own-member assembly for both pairs (independent shfl chains)
        float uA = h ? p1 : p0, vA = h ? p0 : p1;
        float uB = h ? q1 : q0, vB = h ? q0 : q1;
        float AA = uA + __shfl_xor_sync(FULLM, vA, 16);
        float AB = uB + __shfl_xor_sync(FULLM, vB, 16);
        float tA = fmaxf(AA + cconst, 0.f) * w2c;
        float tB = fmaxf(AB + cconst, 0.f) * w2c;

        // interleaved butterflies over the 16 columns of each half
        tA += __shfl_xor_sync(FULLM, tA, 1);
        tB += __shfl_xor_sync(FULLM, tB, 1);
        tA += __shfl_xor_sync(FULLM, tA, 2);
        tB += __shfl_xor_sync(FULLM, tB, 2);
        tA += __shfl_xor_sync(FULLM, tA, 4);
        tB += __shfl_xor_sync(FULLM, tB, 4);
        tA += __shfl_xor_sync(FULLM, tA, 8);
        tB += __shfl_xor_sync(FULLM, tB, 8);

        // own-member weights (two independent exps)
        float eA = (4 * u + h     <= len) ? __expf(tA + b2) : 0.f;
        float eB = (4 * u + 2 + h <= len) ? __expf(tB + b2) : 0.f;
        dsum += eA + eB;
        gq.x = fmaf(eA, curA.x, fmaf(eB, curB.x, gq.x));
        gq.y = fmaf(eA, curA.y, fmaf(eB, curB.y, gq.y));
        gq.z = fmaf(eA, curA.z, fmaf(eB, curB.z, gq.z));
        gq.w = fmaf(eA, curA.w, fmaf(eB, curB.w, gq.w));
    }

    // ---- remainder pair (npairs odd): members 4*nfull + {0,1} in rA ----
    if (npairs & 1) {
        const float4 cur = rA;
        *(float4*)(meb + h * 72 + stoff) = cur;
        __syncwarp();

        const float4* me0 = (const float4*)(meb + h * 36);
        const float4* me1 = (const float4*)(meb + 72 + h * 36);
        float s0[2] = {0.f, 0.f}, s1[2] = {0.f, 0.f};
        #pragma unroll
        for (int i = 0; i < 8; i++) {
            const int par = i & 1;
            float4 x = me0[i];
            s0[par] = fmaf(x.x, wc[4*i+0], s0[par]);
            s0[par] = fmaf(x.y, wc[4*i+1], s0[par]);
            s0[par] = fmaf(x.z, wc[4*i+2], s0[par]);
            s0[par] = fmaf(x.w, wc[4*i+3], s0[par]);
            float4 y = me1[i];
            s1[par] = fmaf(y.x, wc[4*i+0], s1[par]);
            s1[par] = fmaf(y.y, wc[4*i+1], s1[par]);
            s1[par] = fmaf(y.z, wc[4*i+2], s1[par]);
            s1[par] = fmaf(y.w, wc[4*i+3], s1[par]);
        }
        float p0 = s0[0] + s0[1];
        float p1 = s1[0] + s1[1];

        float u2 = h ? p1 : p0, v2 = h ? p0 : p1;
        float A = u2 + __shfl_xor_sync(FULLM, v2, 16);
        float t = fmaxf(A + cconst, 0.f) * w2c;
        t += __shfl_xor_sync(FULLM, t, 1);
        t += __shfl_xor_sync(FULLM, t, 2);
        t += __shfl_xor_sync(FULLM, t, 4);
        t += __shfl_xor_sync(FULLM, t, 8);

        float e = (4 * nfull + h <= len) ? __expf(t + b2) : 0.f;
        dsum += e;
        gq.x = fmaf(e, cur.x, gq.x);
        gq.y = fmaf(e, cur.y, gq.y);
        gq.z = fmaf(e, cur.z, gq.z);
        gq.w = fmaf(e, cur.w, gq.w);
    }

    // ---- cross-half combine: pooled g + group embedding (prefetched) ----
    gq.x += __shfl_xor_sync(FULLM, gq.x, 16);
    gq.y += __shfl_xor_sync(FULLM, gq.y, 16);
    gq.z += __shfl_xor_sync(FULLM, gq.z, 16);
    gq.w += __shfl_xor_sync(FULLM, gq.w, 16);
    dsum += __shfl_xor_sync(FULLM, dsum, 16);
    const float inv = 1.0f / dsum;

    float4 gg, el;
    gg.x = fmaf(gq.x, inv, grp.x);  el.x = gg.x * it4.x;
    gg.y = fmaf(gq.y, inv, grp.y);  el.y = gg.y * it4.y;
    gg.z = fmaf(gq.z, inv, grp.z);  el.z = gg.z * it4.z;
    gg.w = fmaf(gq.w, inv, grp.w);  el.w = gg.w * it4.w;

    // both halves hold identical values; duplicate stores are benign
    ((float4*)&s_new[0])[c0]  = el;   // elem
    ((float4*)&s_new[ND])[c0] = gg;   // g   (item already at s_new[2*ND])
    __syncwarp();

    // ---- predict MLP: new_e[192] -> 8 -> 1 -> sigmoid (float4 LDS) ----
    const int j = lane & 7;        // hidden unit
    const int q = lane >> 3;       // k-quarter (48 elems each)
    float ph = 0.f;
    {
        const float4* sn4 = (const float4*)s_new;
        #pragma unroll
        for (int i = 0; i < 12; i++) {
            float4 a = sn4[q * 12 + i];
            int k = q * 48 + 4 * i;
            ph = fmaf(a.x, pred_w1[k * 8 + j],       ph);
            ph = fmaf(a.y, pred_w1[(k + 1) * 8 + j], ph);
            ph = fmaf(a.z, pred_w1[(k + 2) * 8 + j], ph);
            ph = fmaf(a.w, pred_w1[(k + 3) * 8 + j], ph);
        }
    }
    ph += __shfl_xor_sync(FULLM, ph, 8);
    ph += __shfl_xor_sync(FULLM, ph, 16);

    float hj = fmaxf(ph + pred_b1[j], 0.f);
    float t2 = hj * pred_w2[j];
    t2 += __shfl_xor_sync(FULLM, t2, 1);
    t2 += __shfl_xor_sync(FULLM, t2, 2);
    t2 += __shfl_xor_sync(FULLM, t2, 4);

    if (lane == 0) {
        float z = t2 + pred_b2[0];
        out[b] = 1.0f / (1.0f + __expf(-z));
    }
}

extern "C" void kernel_launch(void* const* d_in, const int* in_sizes, int n_in,
                              void* d_out, int out_size) {
    (void)in_sizes; (void)n_in; (void)out_size;
    agree_kernel<<<NB, 32>>>(
        (const int*)d_in[0],   // group_inputs
        (const int*)d_in[1],   // item_inputs
        (const int*)d_in[2],   // member_ids
        (const int*)d_in[3],   // member_lengths
        (const float*)d_in[4], // user_table
        (const float*)d_in[5], // item_table
        (const float*)d_in[6], // group_table
        (const float*)d_in[7], // att_w1
        (const float*)d_in[8], // att_b1
        (const float*)d_in[9], // att_w2
        (const float*)d_in[10],// att_b2
        (const float*)d_in[11],// pred_w1
        (const float*)d_in[12],// pred_b1
        (const float*)d_in[13],// pred_w2
        (const float*)d_in[14],// pred_b2
        (float*)d_out);
}

// round 15
// speedup vs baseline: 1.2128x; 1.0279x over previous
#include <cuda_runtime.h>
#include <math.h>

#define NB 16384
#define NM 50
#define ND 64
#define FULLM 0xffffffffu

// dots of one 4-member quad staged in `mb` (member stride 72 words):
// P0/P1 = pairA member0/member1 partial dots over this lane's 32-d slice,
// Q0/Q1 = pairB. 2 accumulators per member for FMA-chain depth.
__device__ __forceinline__ void quad_dots(const float* mb, const float* wc, int h,
                                          float& P0, float& P1, float& Q0, float& Q1)
{
    const float4* a0 = (const float4*)(mb + h * 36);
    const float4* a1 = (const float4*)(mb + 72 + h * 36);
    const float4* b0 = (const float4*)(mb + 144 + h * 36);
    const float4* b1 = (const float4*)(mb + 216 + h * 36);
    float sA0[2] = {0.f, 0.f}, sA1[2] = {0.f, 0.f};
    float sB0[2] = {0.f, 0.f}, sB1[2] = {0.f, 0.f};
    #pragma unroll
    for (int i = 0; i < 8; i++) {
        const int p = i & 1;
        float4 x = a0[i];
        sA0[p] = fmaf(x.x, wc[4*i+0], sA0[p]);
        sA0[p] = fmaf(x.y, wc[4*i+1], sA0[p]);
        sA0[p] = fmaf(x.z, wc[4*i+2], sA0[p]);
        sA0[p] = fmaf(x.w, wc[4*i+3], sA0[p]);
        float4 y = a1[i];
        sA1[p] = fmaf(y.x, wc[4*i+0], sA1[p]);
        sA1[p] = fmaf(y.y, wc[4*i+1], sA1[p]);
        sA1[p] = fmaf(y.z, wc[4*i+2], sA1[p]);
        sA1[p] = fmaf(y.w, wc[4*i+3], sA1[p]);
        float4 z = b0[i];
        sB0[p] = fmaf(z.x, wc[4*i+0], sB0[p]);
        sB0[p] = fmaf(z.y, wc[4*i+1], sB0[p]);
        sB0[p] = fmaf(z.z, wc[4*i+2], sB0[p]);
        sB0[p] = fmaf(z.w, wc[4*i+3], sB0[p]);
        float4 w = b1[i];
        sB1[p] = fmaf(w.x, wc[4*i+0], sB1[p]);
        sB1[p] = fmaf(w.y, wc[4*i+1], sB1[p]);
        sB1[p] = fmaf(w.z, wc[4*i+2], sB1[p]);
        sB1[p] = fmaf(w.w, wc[4*i+3], sB1[p]);
    }
    P0 = sA0[0] + sA0[1];
    P1 = sA1[0] + sA1[1];
    Q0 = sB0[0] + sB0[1];
    Q1 = sB1[0] + sB1[1];
}

__global__ __launch_bounds__(32, 20)
void agree_kernel(
    const int* __restrict__ group_inputs,
    const int* __restrict__ item_inputs,
    const int* __restrict__ member_ids,
    const int* __restrict__ member_lengths,
    const float* __restrict__ user_table,
    const float* __restrict__ item_table,
    const float* __restrict__ group_table,
    const float* __restrict__ att_w1,
    const float* __restrict__ att_b1,
    const float* __restrict__ att_w2,
    const float* __restrict__ att_b2,
    const float* __restrict__ pred_w1,
    const float* __restrict__ pred_b1,
    const float* __restrict__ pred_w2,
    const float* __restrict__ pred_b2,
    float* __restrict__ out)
{
    // two quad buffers (4 members each). One member = 72 words:
    // d[0..31] at 0..31, d[32..63] at 36..67 (pad kills bank aliasing).
    __shared__ __align__(16) float s_me[8][72];
    __shared__ __align__(16) float s_new[3 * ND];   // [elem | g | item_e]

    const int lane = threadIdx.x & 31;
    const int b = blockIdx.x;

    const int c0 = lane & 15;   // att hidden unit / float4-chunk this lane owns
    const int h  = lane >> 4;   // d-half AND "own member" (within a pair)

    float* s_item = &s_new[2 * ND];

    // ---- item embedding (float4 per lane; halves write identical data) ----
    const float4 it4 =
        ((const float4*)(item_table + (size_t)item_inputs[b] * ND))[c0];
    ((float4*)s_item)[c0] = it4;
    __syncwarp();

    // ---- all member ids into registers ----
    const int idsA = member_ids[b * NM + lane];
    const int idsB = (lane < NM - 32) ? member_ids[b * NM + 32 + lane] : 0;

    // ---- W1a slice: column c0, d-range [h*32, h*32+32)  (32 regs) ----
    float wc[32];
    #pragma unroll
    for (int k = 0; k < 32; k++) wc[k] = att_w1[(h * 32 + k) * 16 + c0];

    // ---- cconst[c0] = att_b1 + item_e @ W1b, split per d-half + combine ----
    float cconst;
    {
        float cc = 0.f;
        const float4* si4 = (const float4*)(s_item + h * 32);
        #pragma unroll
        for (int dd = 0; dd < 8; dd++) {
            float4 v = si4[dd];
            int db = (ND + h * 32 + 4 * dd) * 16 + c0;
            cc = fmaf(v.x, att_w1[db],      cc);
            cc = fmaf(v.y, att_w1[db + 16], cc);
            cc = fmaf(v.z, att_w1[db + 32], cc);
            cc = fmaf(v.w, att_w1[db + 48], cc);
        }
        cconst = cc + __shfl_xor_sync(FULLM, cc, 16) + att_b1[c0];
    }

    const float w2c = att_w2[c0];
    const float b2  = att_b2[0];
    const int  len  = member_lengths[b];     // member m valid iff m <= len
    const int  npairs = (len >> 1) + 1;
    const int  nfull = (npairs + 1) >> 1;    // quads (phantom pair masked)

    // plain-exp softmax (scores O(0.3) by construction — no max shift)
    float dsum = 0.f;
    float4 gq = make_float4(0.f, 0.f, 0.f, 0.f);

    // ---- preload quad 0: pair0 member h; pair1 member h (or zeros) ----
    float4 rA, rB = make_float4(0.f, 0.f, 0.f, 0.f);
    {
        int mid = __shfl_sync(FULLM, idsA, h);
        rA = ((const float4*)(user_table + (size_t)mid * ND))[c0];
    }
    if (npairs >= 2) {
        int mid = __shfl_sync(FULLM, idsA, 2 + h);
        rB = ((const float4*)(user_table + (size_t)mid * ND))[c0];
    }

    float* const meb = &s_me[0][0];                  // quad stride 288 words
    const int stoff = 4 * c0 + ((c0 >= 8) ? 4 : 0);  // padded store offset

    // ---- pipeline prologue: stage quad0, prefetch quad1, dots0+assemble0 ----
    *(float4*)(meb + h * 72 + stoff)       = rA;
    *(float4*)(meb + 144 + h * 72 + stoff) = rB;
    __syncwarp();
    if (2 < npairs) {
        int mid = __shfl_sync(FULLM, idsA, 4 + h);
        rA = ((const float4*)(user_table + (size_t)mid * ND))[c0];
    }
    if (3 < npairs) {
        int mid = __shfl_sync(FULLM, idsA, 6 + h);
        rB = ((const float4*)(user_table + (size_t)mid * ND))[c0];
    }

    float tA, tB;
    {
        float p0, p1, q0, q1;
        quad_dots(meb, wc, h, p0, p1, q0, q1);
        float uA = h ? p1 : p0, vA = h ? p0 : p1;
        float uB = h ? q1 : q0, vB = h ? q0 : q1;
        float AA = uA + __shfl_xor_sync(FULLM, vA, 16);
        float AB = uB + __shfl_xor_sync(FULLM, vB, 16);
        tA = fmaxf(AA + cconst, 0.f) * w2c;
        tB = fmaxf(AB + cconst, 0.f) * w2c;
    }

    // ---- pipelined main loop: butterfly(u) overlaps dots(u+1) ----
    #pragma unroll 1
    for (int u = 0; u < nfull; u++) {
        float* const nb = meb + ((u + 1) & 1) * 288;
        if (u + 1 < nfull) {
            // stage quad u+1, then prefetch quad u+2
            *(float4*)(nb + h * 72 + stoff)       = rA;
            *(float4*)(nb + 144 + h * 72 + stoff) = rB;
            __syncwarp();
            if (2 * u + 4 < npairs) {
                int m = 4 * u + 8 + h;
                int mid = __shfl_sync(FULLM, (m < 32) ? idsA : idsB, m & 31);
                rA = ((const float4*)(user_table + (size_t)mid * ND))[c0];
            }
            if (2 * u + 5 < npairs) {
                int m = 4 * u + 10 + h;
                int mid = __shfl_sync(FULLM, (m < 32) ? idsA : idsB, m & 31);
                rB = ((const float4*)(user_table + (size_t)mid * ND))[c0];
            }
        }

        // one straight-line block: next-quad dots + current butterfly.
        // (Last iteration reads stale data; results discarded below.)
        float pn0, pn1, qn0, qn1;
        quad_dots(nb, wc, h, pn0, pn1, qn0, qn1);
        tA += __shfl_xor_sync(FULLM, tA, 1);
        tB += __shfl_xor_sync(FULLM, tB, 1);
        tA += __shfl_xor_sync(FULLM, tA, 2);
        tB += __shfl_xor_sync(FULLM, tB, 2);
        tA += __shfl_xor_sync(FULLM, tA, 4);
        tB += __shfl_xor_sync(FULLM, tB, 4);
        tA += __shfl_xor_sync(FULLM, tA, 8);
        tB += __shfl_xor_sync(FULLM, tB, 8);

        // own-member weights; phantom/invalid members masked to 0
        float eA = (4 * u + h     <= len) ? __expf(tA + b2) : 0.f;
        float eB = (4 * u + 2 + h <= len) ? __expf(tB + b2) : 0.f;
        dsum += eA + eB;

        // reload own chunks of quad u (buffer intact until next staging)
        const float* cb = meb + (u & 1) * 288;
        float4 curA = *(const float4*)(cb + h * 72 + stoff);
        float4 curB = *(const float4*)(cb + 144 + h * 72 + stoff);
        gq.x = fmaf(eA, curA.x, fmaf(eB, curB.x, gq.x));
        gq.y = fmaf(eA, curA.y, fmaf(eB, curB.y, gq.y));
        gq.z = fmaf(eA, curA.z, fmaf(eB, curB.z, gq.z));
        gq.w = fmaf(eA, curA.w, fmaf(eB, curB.w, gq.w));

        // assemble next quad's scores (garbage on last iteration — unused)
        float uA = h ? pn1 : pn0, vA = h ? pn0 : pn1;
        float uB = h ? qn1 : qn0, vB = h ? qn0 : qn1;
        float AA = uA + __shfl_xor_sync(FULLM, vA, 16);
        float AB = uB + __shfl_xor_sync(FULLM, vB, 16);
        tA = fmaxf(AA + cconst, 0.f) * w2c;
        tB = fmaxf(AB + cconst, 0.f) * w2c;
    }

    // ---- cross-half combine: pooled g + group embedding ----
    gq.x += __shfl_xor_sync(FULLM, gq.x, 16);
    gq.y += __shfl_xor_sync(FULLM, gq.y, 16);
    gq.z += __shfl_xor_sync(FULLM, gq.z, 16);
    gq.w += __shfl_xor_sync(FULLM, gq.w, 16);
    dsum += __shfl_xor_sync(FULLM, dsum, 16);
    const float inv = 1.0f / dsum;

    const size_t gid = (size_t)group_inputs[b];
    float4 grp = ((const float4*)(group_table + gid * ND))[c0];

    float4 gg, el;
    gg.x = fmaf(gq.x, inv, grp.x);  el.x = gg.x * it4.x;
    gg.y = fmaf(gq.y, inv, grp.y);  el.y = gg.y * it4.y;
    gg.z = fmaf(gq.z, inv, grp.z);  el.z = gg.z * it4.z;
    gg.w = fmaf(gq.w, inv, grp.w);  el.w = gg.w * it4.w;

    // both halves hold identical values; duplicate stores are benign
    ((float4*)&s_new[0])[c0]  = el;   // elem
    ((float4*)&s_new[ND])[c0] = gg;   // g   (item already at s_new[2*ND])
    __syncwarp();

    // ---- predict MLP: new_e[192] -> 8 -> 1 -> sigmoid ----
    const int j = lane & 7;        // hidden unit
    const int q = lane >> 3;       // k-quarter (48 elems each)
    float ph = 0.f;
    #pragma unroll 12
    for (int i = 0; i < 48; i++) {
        int k = q * 48 + i;
        ph = fmaf(s_new[k], pred_w1[k * 8 + j], ph);
    }
    ph += __shfl_xor_sync(FULLM, ph, 8);
    ph += __shfl_xor_sync(FULLM, ph, 16);

    float hj = fmaxf(ph + pred_b1[j], 0.f);
    float t2 = hj * pred_w2[j];
    t2 += __shfl_xor_sync(FULLM, t2, 1);
    t2 += __shfl_xor_sync(FULLM, t2, 2);
    t2 += __shfl_xor_sync(FULLM, t2, 4);

    if (lane == 0) {
        float z = t2 + pred_b2[0];
        out[b] = 1.0f / (1.0f + __expf(-z));
    }
}

extern "C" void kernel_launch(void* const* d_in, const int* in_sizes, int n_in,
                              void* d_out, int out_size) {
    (void)in_sizes; (void)n_in; (void)out_size;
    agree_kernel<<<NB, 32>>>(
        (const int*)d_in[0],   // group_inputs
        (const int*)d_in[1],   // item_inputs
        (const int*)d_in[2],   // member_ids
        (const int*)d_in[3],   // member_lengths
        (const float*)d_in[4], // user_table
        (const float*)d_in[5], // item_table
        (const float*)d_in[6], // group_table
        (const float*)d_in[7], // att_w1
        (const float*)d_in[8], // att_b1
        (const float*)d_in[9], // att_w2
        (const float*)d_in[10],// att_b2
        (const float*)d_in[11],// pred_w1
        (const float*)d_in[12],// pred_b1
        (const float*)d_in[13],// pred_w2
        (const float*)d_in[14],// pred_b2
        (float*)d_out);
}

// round 16
// speedup vs baseline: 1.2863x; 1.0606x over previous
#include <cuda_runtime.h>
#include <math.h>

#define NB 16384
#define NM 50
#define ND 64
#define FULLM 0xffffffffu

// dots of one 4-member quad staged in `mb` (member stride 72 words):
// P0/P1 = pairA member0/member1 partial dots over this lane's 32-d slice,
// Q0/Q1 = pairB. 2 accumulators per member for FMA-chain depth.
__device__ __forceinline__ void quad_dots(const float* mb, const float* wc, int h,
                                          float& P0, float& P1, float& Q0, float& Q1)
{
    const float4* a0 = (const float4*)(mb + h * 36);
    const float4* a1 = (const float4*)(mb + 72 + h * 36);
    const float4* b0 = (const float4*)(mb + 144 + h * 36);
    const float4* b1 = (const float4*)(mb + 216 + h * 36);
    float sA0[2] = {0.f, 0.f}, sA1[2] = {0.f, 0.f};
    float sB0[2] = {0.f, 0.f}, sB1[2] = {0.f, 0.f};
    #pragma unroll
    for (int i = 0; i < 8; i++) {
        const int p = i & 1;
        float4 x = a0[i];
        sA0[p] = fmaf(x.x, wc[4*i+0], sA0[p]);
        sA0[p] = fmaf(x.y, wc[4*i+1], sA0[p]);
        sA0[p] = fmaf(x.z, wc[4*i+2], sA0[p]);
        sA0[p] = fmaf(x.w, wc[4*i+3], sA0[p]);
        float4 y = a1[i];
        sA1[p] = fmaf(y.x, wc[4*i+0], sA1[p]);
        sA1[p] = fmaf(y.y, wc[4*i+1], sA1[p]);
        sA1[p] = fmaf(y.z, wc[4*i+2], sA1[p]);
        sA1[p] = fmaf(y.w, wc[4*i+3], sA1[p]);
        float4 z = b0[i];
        sB0[p] = fmaf(z.x, wc[4*i+0], sB0[p]);
        sB0[p] = fmaf(z.y, wc[4*i+1], sB0[p]);
        sB0[p] = fmaf(z.z, wc[4*i+2], sB0[p]);
        sB0[p] = fmaf(z.w, wc[4*i+3], sB0[p]);
        float4 w = b1[i];
        sB1[p] = fmaf(w.x, wc[4*i+0], sB1[p]);
        sB1[p] = fmaf(w.y, wc[4*i+1], sB1[p]);
        sB1[p] = fmaf(w.z, wc[4*i+2], sB1[p]);
        sB1[p] = fmaf(w.w, wc[4*i+3], sB1[p]);
    }
    P0 = sA0[0] + sA0[1];
    P1 = sA1[0] + sA1[1];
    Q0 = sB0[0] + sB0[1];
    Q1 = sB1[0] + sB1[1];
}

__global__ __launch_bounds__(32, 20)
void agree_kernel(
    const int* __restrict__ group_inputs,
    const int* __restrict__ item_inputs,
    const int* __restrict__ member_ids,
    const int* __restrict__ member_lengths,
    const float* __restrict__ user_table,
    const float* __restrict__ item_table,
    const float* __restrict__ group_table,
    const float* __restrict__ att_w1,
    const float* __restrict__ att_b1,
    const float* __restrict__ att_w2,
    const float* __restrict__ att_b2,
    const float* __restrict__ pred_w1,
    const float* __restrict__ pred_b1,
    const float* __restrict__ pred_w2,
    const float* __restrict__ pred_b2,
    float* __restrict__ out)
{
    // two quad buffers (4 members each). One member = 72 words:
    // d[0..31] at 0..31, d[32..63] at 36..67 (pad kills bank aliasing).
    __shared__ __align__(16) float s_me[8][72];
    __shared__ __align__(16) float s_new[3 * ND];   // [elem | g | item_e]

    const int lane = threadIdx.x & 31;
    const int b = blockIdx.x;

    const int c0 = lane & 15;   // att hidden unit / float4-chunk this lane owns
    const int h  = lane >> 4;   // d-half AND "own member" (within a pair)

    float* s_item = &s_new[2 * ND];

    // ---- item embedding (float4 per lane; halves write identical data) ----
    const float4 it4 =
        ((const float4*)(item_table + (size_t)item_inputs[b] * ND))[c0];
    ((float4*)s_item)[c0] = it4;
    __syncwarp();

    // ---- all member ids into registers ----
    const int idsA = member_ids[b * NM + lane];
    const int idsB = (lane < NM - 32) ? member_ids[b * NM + 32 + lane] : 0;

    // ---- W1a slice: column c0, d-range [h*32, h*32+32)  (32 regs) ----
    float wc[32];
    #pragma unroll
    for (int k = 0; k < 32; k++) wc[k] = att_w1[(h * 32 + k) * 16 + c0];

    // ---- cconst[c0] = att_b1 + item_e @ W1b, split per d-half + combine ----
    float cconst;
    {
        float cc = 0.f;
        const float4* si4 = (const float4*)(s_item + h * 32);
        #pragma unroll
        for (int dd = 0; dd < 8; dd++) {
            float4 v = si4[dd];
            int db = (ND + h * 32 + 4 * dd) * 16 + c0;
            cc = fmaf(v.x, att_w1[db],      cc);
            cc = fmaf(v.y, att_w1[db + 16], cc);
            cc = fmaf(v.z, att_w1[db + 32], cc);
            cc = fmaf(v.w, att_w1[db + 48], cc);
        }
        cconst = cc + __shfl_xor_sync(FULLM, cc, 16) + att_b1[c0];
    }

    const float w2c = att_w2[c0];
    const float b2  = att_b2[0];
    const int  len  = member_lengths[b];     // member m valid iff m <= len
    const int  npairs = (len >> 1) + 1;
    const int  nfull = (npairs + 1) >> 1;    // quads (phantom pair masked)

    // plain-exp softmax (scores O(0.3) by construction — no max shift)
    float dsum = 0.f;
    float4 gq = make_float4(0.f, 0.f, 0.f, 0.f);

    // ---- preload quad 0: pair0 member h; pair1 member h (or zeros) ----
    float4 rA, rB = make_float4(0.f, 0.f, 0.f, 0.f);
    {
        int mid = __shfl_sync(FULLM, idsA, h);
        rA = ((const float4*)(user_table + (size_t)mid * ND))[c0];
    }
    if (npairs >= 2) {
        int mid = __shfl_sync(FULLM, idsA, 2 + h);
        rB = ((const float4*)(user_table + (size_t)mid * ND))[c0];
    }

    float* const meb = &s_me[0][0];                  // quad stride 288 words
    const int stoff = 4 * c0 + ((c0 >= 8) ? 4 : 0);  // padded store offset

    // ---- pipeline prologue: stage quad0, prefetch quad1, dots0+assemble0 ----
    *(float4*)(meb + h * 72 + stoff)       = rA;
    *(float4*)(meb + 144 + h * 72 + stoff) = rB;
    __syncwarp();
    if (2 < npairs) {
        int mid = __shfl_sync(FULLM, idsA, 4 + h);
        rA = ((const float4*)(user_table + (size_t)mid * ND))[c0];
    }
    if (3 < npairs) {
        int mid = __shfl_sync(FULLM, idsA, 6 + h);
        rB = ((const float4*)(user_table + (size_t)mid * ND))[c0];
    }

    float tA, tB;
    {
        float p0, p1, q0, q1;
        quad_dots(meb, wc, h, p0, p1, q0, q1);
        float uA = h ? p1 : p0, vA = h ? p0 : p1;
        float uB = h ? q1 : q0, vB = h ? q0 : q1;
        float AA = uA + __shfl_xor_sync(FULLM, vA, 16);
        float AB = uB + __shfl_xor_sync(FULLM, vB, 16);
        tA = fmaxf(AA + cconst, 0.f) * w2c;
        tB = fmaxf(AB + cconst, 0.f) * w2c;
    }

    // ---- pipelined main loop (peeled last iter): dots(u+1) overlaps
    //      butterfly(u); every dots block computes real data ----
    #pragma unroll 1
    for (int u = 0; u < nfull - 1; u++) {
        float* const nb = meb + ((u + 1) & 1) * 288;

        // stage quad u+1, then prefetch quad u+2
        *(float4*)(nb + h * 72 + stoff)       = rA;
        *(float4*)(nb + 144 + h * 72 + stoff) = rB;
        __syncwarp();
        if (2 * u + 4 < npairs) {
            int m = 4 * u + 8 + h;
            int mid = __shfl_sync(FULLM, (m < 32) ? idsA : idsB, m & 31);
            rA = ((const float4*)(user_table + (size_t)mid * ND))[c0];
        }
        if (2 * u + 5 < npairs) {
            int m = 4 * u + 10 + h;
            int mid = __shfl_sync(FULLM, (m < 32) ? idsA : idsB, m & 31);
            rB = ((const float4*)(user_table + (size_t)mid * ND))[c0];
        }

        // one straight-line block: dots(u+1) + butterfly(u) interleave
        float pn0, pn1, qn0, qn1;
        quad_dots(nb, wc, h, pn0, pn1, qn0, qn1);
        tA += __shfl_xor_sync(FULLM, tA, 1);
        tB += __shfl_xor_sync(FULLM, tB, 1);
        tA += __shfl_xor_sync(FULLM, tA, 2);
        tB += __shfl_xor_sync(FULLM, tB, 2);
        tA += __shfl_xor_sync(FULLM, tA, 4);
        tB += __shfl_xor_sync(FULLM, tB, 4);
        tA += __shfl_xor_sync(FULLM, tA, 8);
        tB += __shfl_xor_sync(FULLM, tB, 8);

        // own-member weights of quad u; invalid members masked to 0
        float eA = (4 * u + h     <= len) ? __expf(tA + b2) : 0.f;
        float eB = (4 * u + 2 + h <= len) ? __expf(tB + b2) : 0.f;
        dsum += eA + eB;

        // reload own chunks of quad u (buffer intact until next staging)
        const float* cb = meb + (u & 1) * 288;
        float4 curA = *(const float4*)(cb + h * 72 + stoff);
        float4 curB = *(const float4*)(cb + 144 + h * 72 + stoff);
        gq.x = fmaf(eA, curA.x, fmaf(eB, curB.x, gq.x));
        gq.y = fmaf(eA, curA.y, fmaf(eB, curB.y, gq.y));
        gq.z = fmaf(eA, curA.z, fmaf(eB, curB.z, gq.z));
        gq.w = fmaf(eA, curA.w, fmaf(eB, curB.w, gq.w));

        // assemble quad u+1's pre-butterfly scores
        float uA = h ? pn1 : pn0, vA = h ? pn0 : pn1;
        float uB = h ? qn1 : qn0, vB = h ? qn0 : qn1;
        float AA = uA + __shfl_xor_sync(FULLM, vA, 16);
        float AB = uB + __shfl_xor_sync(FULLM, vB, 16);
        tA = fmaxf(AA + cconst, 0.f) * w2c;
        tB = fmaxf(AB + cconst, 0.f) * w2c;
    }

    // ---- peeled final quad (no dots, no staging — pure drain) ----
    {
        const int u = nfull - 1;
        tA += __shfl_xor_sync(FULLM, tA, 1);
        tB += __shfl_xor_sync(FULLM, tB, 1);
        tA += __shfl_xor_sync(FULLM, tA, 2);
        tB += __shfl_xor_sync(FULLM, tB, 2);
        tA += __shfl_xor_sync(FULLM, tA, 4);
        tB += __shfl_xor_sync(FULLM, tB, 4);
        tA += __shfl_xor_sync(FULLM, tA, 8);
        tB += __shfl_xor_sync(FULLM, tB, 8);

        float eA = (4 * u + h     <= len) ? __expf(tA + b2) : 0.f;
        float eB = (4 * u + 2 + h <= len) ? __expf(tB + b2) : 0.f;
        dsum += eA + eB;

        const float* cb = meb + (u & 1) * 288;
        float4 curA = *(const float4*)(cb + h * 72 + stoff);
        float4 curB = *(const float4*)(cb + 144 + h * 72 + stoff);
        gq.x = fmaf(eA, curA.x, fmaf(eB, curB.x, gq.x));
        gq.y = fmaf(eA, curA.y, fmaf(eB, curB.y, gq.y));
        gq.z = fmaf(eA, curA.z, fmaf(eB, curB.z, gq.z));
        gq.w = fmaf(eA, curA.w, fmaf(eB, curB.w, gq.w));
    }

    // ---- cross-half combine: pooled g + group embedding ----
    gq.x += __shfl_xor_sync(FULLM, gq.x, 16);
    gq.y += __shfl_xor_sync(FULLM, gq.y, 16);
    gq.z += __shfl_xor_sync(FULLM, gq.z, 16);
    gq.w += __shfl_xor_sync(FULLM, gq.w, 16);
    dsum += __shfl_xor_sync(FULLM, dsum, 16);
    const float inv = 1.0f / dsum;

    const size_t gid = (size_t)group_inputs[b];
    float4 grp = ((const float4*)(group_table + gid * ND))[c0];

    float4 gg, el;
    gg.x = fmaf(gq.x, inv, grp.x);  el.x = gg.x * it4.x;
    gg.y = fmaf(gq.y, inv, grp.y);  el.y = gg.y * it4.y;
    gg.z = fmaf(gq.z, inv, grp.z);  el.z = gg.z * it4.z;
    gg.w = fmaf(gq.w, inv, grp.w);  el.w = gg.w * it4.w;

    // both halves hold identical values; duplicate stores are benign
    ((float4*)&s_new[0])[c0]  = el;   // elem
    ((float4*)&s_new[ND])[c0] = gg;   // g   (item already at s_new[2*ND])
    __syncwarp();

    // ---- predict MLP: new_e[192] -> 8 -> 1 -> sigmoid ----
    const int j = lane & 7;        // hidden unit
    const int q = lane >> 3;       // k-quarter (48 elems each)
    float ph = 0.f;
    #pragma unroll 12
    for (int i = 0; i < 48; i++) {
        int k = q * 48 + i;
        ph = fmaf(s_new[k], pred_w1[k * 8 + j], ph);
    }
    ph += __shfl_xor_sync(FULLM, ph, 8);
    ph += __shfl_xor_sync(FULLM, ph, 16);

    float hj = fmaxf(ph + pred_b1[j], 0.f);
    float t2 = hj * pred_w2[j];
    t2 += __shfl_xor_sync(FULLM, t2, 1);
    t2 += __shfl_xor_sync(FULLM, t2, 2);
    t2 += __shfl_xor_sync(FULLM, t2, 4);

    if (lane == 0) {
        float z = t2 + pred_b2[0];
        out[b] = 1.0f / (1.0f + __expf(-z));
    }
}

extern "C" void kernel_launch(void* const* d_in, const int* in_sizes, int n_in,
                              void* d_out, int out_size) {
    (void)in_sizes; (void)n_in; (void)out_size;
    agree_kernel<<<NB, 32>>>(
        (const int*)d_in[0],   // group_inputs
        (const int*)d_in[1],   // item_inputs
        (const int*)d_in[2],   // member_ids
        (const int*)d_in[3],   // member_lengths
        (const float*)d_in[4], // user_table
        (const float*)d_in[5], // item_table
        (const float*)d_in[6], // group_table
        (const float*)d_in[7], // att_w1
        (const float*)d_in[8], // att_b1
        (const float*)d_in[9], // att_w2
        (const float*)d_in[10],// att_b2
        (const float*)d_in[11],// pred_w1
        (const float*)d_in[12],// pred_b1
        (const float*)d_in[13],// pred_w2
        (const float*)d_in[14],// pred_b2
        (float*)d_out);
}